// round 4
// baseline (speedup 1.0000x reference)
#include <cuda_runtime.h>
#include <float.h>

typedef unsigned int u32;
typedef unsigned long long u64;

#define NVOX 262144
#define MAXN 1572864
#define PMX (-74.88f)
#define PMY (-74.88f)
#define PMZ (-2.0f)
#define VS  (0.32f)
#define BN_EPS 1e-3f

// ---------------- device scratch (no allocation allowed) --------------------
static __device__ int    g_cnt[NVOX];
static __device__ int    g_start[NVOX];
static __device__ int    g_cursor[NVOX];
static __device__ int    g_bsum[512];
static __device__ int    g_bsumx[512];
static __device__ float4 g_pts[MAXN];       // CSR-ordered (x,y,z,feat)
static __device__ float4 g_vmean[NVOX];
static __device__ float  g_rawmax1[NVOX * 32];
static __device__ float  g_rawmax2[NVOX * 64];
static __device__ float  g_st1[48];         // [0:32) sumsq(y1), [32:43) sum_f
static __device__ float  g_st2[128];        // [0:64) sumsq(y2), [64:128) sum_x
static __device__ float  g_ab1[64];         // [a32 | c32]
static __device__ float  g_ab2[128];        // [a64 | c64]

// ---------------- packed f32x2 (FFMA2: 2x fp32 rate) ------------------------
__device__ __forceinline__ u64 pk2(float a, float b) {
    u64 r; asm("mov.b64 %0,{%1,%2};" : "=l"(r) : "f"(a), "f"(b)); return r;
}
__device__ __forceinline__ void upk2(u64 v, float& a, float& b) {
    asm("mov.b64 {%0,%1},%2;" : "=f"(a), "=f"(b) : "l"(v));
}
__device__ __forceinline__ u64 fma2(u64 a, u64 b, u64 c) {
    u64 d; asm("fma.rn.f32x2 %0,%1,%2,%3;" : "=l"(d) : "l"(a), "l"(b), "l"(c)); return d;
}
__device__ __forceinline__ u64 add2(u64 a, u64 b) {
    u64 d; asm("add.rn.f32x2 %0,%1,%2;" : "=l"(d) : "l"(a), "l"(b)); return d;
}

// ---------------- per-point 11-feature build --------------------------------
__device__ __forceinline__ void build_feat(float4 q, float mx, float my, float mz,
                                           float f[11])
{
    float px = q.x, py = q.y, pz = q.z;
    float cx = floorf((px - PMX) / VS);
    float cy = floorf((py - PMY) / VS);
    float cz = floorf((pz - PMZ) / VS);
    f[0] = px; f[1] = py; f[2] = pz; f[3] = q.w;
    f[4] = px - mx; f[5] = py - my; f[6] = pz - mz;
    f[7] = px - (cx * VS + (0.5f * VS + PMX));
    f[8] = py - (cy * VS + (0.5f * VS + PMY));
    f[9] = pz - (cz * VS + (0.5f * VS + PMZ));
    f[10] = sqrtf(px * px + py * py + pz * pz);
}

// y1 = f @ w1 (32 channels as 16 packed f32x2)
__device__ __forceinline__ void mm1(const u64* __restrict__ s_w1,
                                    const float f[11], u64 y[16])
{
#pragma unroll
    for (int j = 0; j < 16; j++) y[j] = 0ull;
#pragma unroll
    for (int k = 0; k < 11; k++) {
        u64 xk = pk2(f[k], f[k]);
#pragma unroll
        for (int j = 0; j < 16; j++) y[j] = fma2(xk, s_w1[k * 16 + j], y[j]);
    }
}

// ---------------- block reduce-add helper (block = 128 threads) -------------
template <int NVAL>
__device__ __forceinline__ void block_reduce_add(const float (&vals)[NVAL],
                                                 float* smem, float* gdst, int tid)
{
    int lane = tid & 31, wid = tid >> 5;
#pragma unroll
    for (int j = 0; j < NVAL; j++) {
        float v = vals[j];
#pragma unroll
        for (int o = 16; o > 0; o >>= 1) v += __shfl_xor_sync(0xffffffffu, v, o);
        if (lane == 0) smem[wid * NVAL + j] = v;
    }
    __syncthreads();
    if (tid < NVAL)
        atomicAdd(&gdst[tid],
                  smem[tid] + smem[NVAL + tid] + smem[2 * NVAL + tid] + smem[3 * NVAL + tid]);
}

// ---------------- CSR build --------------------------------------------------
__global__ void __launch_bounds__(256) k_hist(const int* __restrict__ uinv, int n) {
    int stride = gridDim.x * 256;
    for (int i = blockIdx.x * 256 + threadIdx.x; i < n; i += stride)
        atomicAdd(&g_cnt[uinv[i]], 1);
}

__global__ void __launch_bounds__(512) k_scanA() {   // grid 512
    __shared__ int sh[512];
    int t = threadIdx.x, g = blockIdx.x * 512 + t;
    int v = g_cnt[g];
    sh[t] = v;
    __syncthreads();
#pragma unroll
    for (int o = 1; o < 512; o <<= 1) {
        int add = (t >= o) ? sh[t - o] : 0;
        __syncthreads();
        sh[t] += add;
        __syncthreads();
    }
    g_start[g] = sh[t] - v;                 // exclusive within block
    if (t == 511) g_bsum[blockIdx.x] = sh[t];
}

__global__ void __launch_bounds__(512) k_scanB() {   // grid 1
    __shared__ int sh[512];
    int t = threadIdx.x;
    int v = g_bsum[t];
    sh[t] = v;
    __syncthreads();
#pragma unroll
    for (int o = 1; o < 512; o <<= 1) {
        int add = (t >= o) ? sh[t - o] : 0;
        __syncthreads();
        sh[t] += add;
        __syncthreads();
    }
    g_bsumx[t] = sh[t] - v;
}

__global__ void __launch_bounds__(512) k_scanC() {   // grid 512
    int g = blockIdx.x * 512 + threadIdx.x;
    int s = g_start[g] + g_bsumx[blockIdx.x];
    g_start[g] = s;
    g_cursor[g] = s;
}

__global__ void __launch_bounds__(256) k_scatter(
    const float* __restrict__ xyz, const float* __restrict__ pf,
    const int* __restrict__ uinv, int n)
{
    int stride = gridDim.x * 256;
    for (int i = blockIdx.x * 256 + threadIdx.x; i < n; i += stride) {
        int v = uinv[i];
        int pos = atomicAdd(&g_cursor[v], 1);
        g_pts[pos] = make_float4(xyz[3 * i + 0], xyz[3 * i + 1], xyz[3 * i + 2], pf[i]);
    }
}

// ---------------- pass 1: per-voxel vmean + y1 stats + raw segmax -----------
__global__ void __launch_bounds__(128) k_pass1(const float* __restrict__ w1) {
    __shared__ u64 s_w1[176];
    __shared__ float s_red[4 * 43];
    int tid = threadIdx.x;
    for (int t = tid; t < 176; t += 128) s_w1[t] = ((const u64*)w1)[t];
    __syncthreads();

    int v = blockIdx.x * 128 + tid;
    int s = g_start[v], c = g_cnt[v];

    // voxel mean (tiny sequential loop, deterministic per CSR order)
    float mx = 0.f, my = 0.f, mz = 0.f;
    for (int p = s; p < s + c; p++) {
        float4 q = g_pts[p];
        mx += q.x; my += q.y; mz += q.z;
    }
    float inv = 1.0f / fmaxf((float)c, 1.0f);
    mx *= inv; my *= inv; mz *= inv;
    g_vmean[v] = make_float4(mx, my, mz, 0.f);

    float maxv[32];
#pragma unroll
    for (int j = 0; j < 32; j++) maxv[j] = -FLT_MAX;
    u64 sq[16];
#pragma unroll
    for (int j = 0; j < 16; j++) sq[j] = 0ull;
    float sf[11];
#pragma unroll
    for (int k = 0; k < 11; k++) sf[k] = 0.f;

    for (int p = s; p < s + c; p++) {
        float4 q = g_pts[p];
        float f[11]; build_feat(q, mx, my, mz, f);
#pragma unroll
        for (int k = 0; k < 11; k++) sf[k] += f[k];
        u64 y[16]; mm1(s_w1, f, y);
#pragma unroll
        for (int j = 0; j < 16; j++) {
            sq[j] = fma2(y[j], y[j], sq[j]);
            float a, b; upk2(y[j], a, b);
            maxv[2 * j]     = fmaxf(maxv[2 * j], a);
            maxv[2 * j + 1] = fmaxf(maxv[2 * j + 1], b);
        }
    }

    float4* rm = (float4*)(g_rawmax1 + (size_t)v * 32);
#pragma unroll
    for (int q8 = 0; q8 < 8; q8++)
        rm[q8] = make_float4(maxv[4 * q8], maxv[4 * q8 + 1], maxv[4 * q8 + 2], maxv[4 * q8 + 3]);

    float vals[43];
#pragma unroll
    for (int j = 0; j < 16; j++) { upk2(sq[j], vals[2 * j], vals[2 * j + 1]); }
#pragma unroll
    for (int k = 0; k < 11; k++) vals[32 + k] = sf[k];
    block_reduce_add<43>(vals, s_red, g_st1, tid);
}

// ---------------- fin1: BN affine params, layer 1 (mu via sum_f @ W1) -------
__global__ void k_fin1(const float* __restrict__ g, const float* __restrict__ b,
                       const float* __restrict__ w1, float invn)
{
    int c = threadIdx.x;  // 32
    float mu = 0.f;
#pragma unroll
    for (int k = 0; k < 11; k++) mu += g_st1[32 + k] * w1[k * 32 + c];
    mu *= invn;
    float m2 = g_st1[c] * invn;
    double var = (double)m2 - (double)mu * (double)mu;
    if (var < 0.0) var = 0.0;
    float a = (float)((double)g[c] / sqrt(var + (double)BN_EPS));
    g_ab1[c] = a;
    g_ab1[32 + c] = fmaf(-mu, a, b[c]);
}

// ---------------- pass 2: per-voxel layer-2 GEMM + stats + raw segmax -------
__global__ void __launch_bounds__(128) k_pass2(const float* __restrict__ w1,
                                               const float* __restrict__ w2)
{
    __shared__ u64 s_w2[2048];   // w2 row k, channel-pair j: [k*32 + j]
    __shared__ u64 s_w1[176];
    __shared__ float s_ab[64];
    __shared__ float s_red[4 * 64];
    int tid = threadIdx.x;
    for (int t = tid; t < 2048; t += 128) s_w2[t] = ((const u64*)w2)[t];
    for (int t = tid; t < 176; t += 128) s_w1[t] = ((const u64*)w1)[t];
    if (tid < 64) s_ab[tid] = g_ab1[tid];
    __syncthreads();

    int v = blockIdx.x * 128 + tid;
    int s = g_start[v], c = g_cnt[v];
    float4 vm = g_vmean[v];
    const float4* rm1 = (const float4*)(g_rawmax1 + (size_t)v * 32);

#pragma unroll
    for (int h = 0; h < 2; h++) {
        // constant half of the GEMM: y2 += xmax @ W2[32:64, h*32:h*32+32]
        u64 cacc[16];
#pragma unroll
        for (int j = 0; j < 16; j++) cacc[j] = 0ull;
        {
#pragma unroll
            for (int q8 = 0; q8 < 8; q8++) {
                float4 r = rm1[q8];
                float xk0 = fmaxf(fmaf(s_ab[4 * q8 + 0], r.x, s_ab[32 + 4 * q8 + 0]), 0.f);
                float xk1 = fmaxf(fmaf(s_ab[4 * q8 + 1], r.y, s_ab[32 + 4 * q8 + 1]), 0.f);
                float xk2 = fmaxf(fmaf(s_ab[4 * q8 + 2], r.z, s_ab[32 + 4 * q8 + 2]), 0.f);
                float xk3 = fmaxf(fmaf(s_ab[4 * q8 + 3], r.w, s_ab[32 + 4 * q8 + 3]), 0.f);
                const u64* wr0 = &s_w2[(32 + 4 * q8 + 0) * 32 + h * 16];
                const u64* wr1 = &s_w2[(32 + 4 * q8 + 1) * 32 + h * 16];
                const u64* wr2 = &s_w2[(32 + 4 * q8 + 2) * 32 + h * 16];
                const u64* wr3 = &s_w2[(32 + 4 * q8 + 3) * 32 + h * 16];
                u64 p0 = pk2(xk0, xk0), p1 = pk2(xk1, xk1);
                u64 p2 = pk2(xk2, xk2), p3 = pk2(xk3, xk3);
#pragma unroll
                for (int j = 0; j < 16; j++) {
                    cacc[j] = fma2(p0, wr0[j], cacc[j]);
                    cacc[j] = fma2(p1, wr1[j], cacc[j]);
                    cacc[j] = fma2(p2, wr2[j], cacc[j]);
                    cacc[j] = fma2(p3, wr3[j], cacc[j]);
                }
            }
        }

        u64 sq[16];
        float mx2[32];
        u64 sxl[16];
#pragma unroll
        for (int j = 0; j < 16; j++) { sq[j] = 0ull; sxl[j] = 0ull; }
#pragma unroll
        for (int j = 0; j < 32; j++) mx2[j] = -FLT_MAX;

        for (int p = s; p < s + c; p++) {
            float4 q = g_pts[p];
            float f[11]; build_feat(q, vm.x, vm.y, vm.z, f);
            u64 y[16]; mm1(s_w1, f, y);
            float x[32];
#pragma unroll
            for (int j = 0; j < 16; j++) {
                float ya, yb; upk2(y[j], ya, yb);
                x[2 * j]     = fmaxf(fmaf(s_ab[2 * j],     ya, s_ab[32 + 2 * j]),     0.f);
                x[2 * j + 1] = fmaxf(fmaf(s_ab[2 * j + 1], yb, s_ab[32 + 2 * j + 1]), 0.f);
            }
            if (h == 0) {
#pragma unroll
                for (int j = 0; j < 16; j++)
                    sxl[j] = add2(sxl[j], pk2(x[2 * j], x[2 * j + 1]));
            }
            u64 acc[16];
#pragma unroll
            for (int j = 0; j < 16; j++) acc[j] = cacc[j];
#pragma unroll
            for (int k = 0; k < 32; k++) {
                u64 xk = pk2(x[k], x[k]);
                const u64* wr = &s_w2[k * 32 + h * 16];
#pragma unroll
                for (int j = 0; j < 16; j++) acc[j] = fma2(xk, wr[j], acc[j]);
            }
#pragma unroll
            for (int j = 0; j < 16; j++) {
                sq[j] = fma2(acc[j], acc[j], sq[j]);
                float a, b; upk2(acc[j], a, b);
                mx2[2 * j]     = fmaxf(mx2[2 * j], a);
                mx2[2 * j + 1] = fmaxf(mx2[2 * j + 1], b);
            }
        }

        // store raw voxel max (empty voxels keep -FLT_MAX -> relu clamps to 0)
        float4* rm2 = (float4*)(g_rawmax2 + (size_t)v * 64 + h * 32);
#pragma unroll
        for (int q8 = 0; q8 < 8; q8++)
            rm2[q8] = make_float4(mx2[4 * q8], mx2[4 * q8 + 1], mx2[4 * q8 + 2], mx2[4 * q8 + 3]);

        // reductions
        {
            float v32[32];
#pragma unroll
            for (int j = 0; j < 16; j++) upk2(sq[j], v32[2 * j], v32[2 * j + 1]);
            __syncthreads();
            block_reduce_add<32>(v32, s_red, g_st2 + h * 32, tid);
        }
        if (h == 0) {
            float v64[64];
#pragma unroll
            for (int j = 0; j < 16; j++) upk2(sxl[j], v64[2 * j], v64[2 * j + 1]);
            float cf = (float)c;
#pragma unroll
            for (int q8 = 0; q8 < 8; q8++) {
                float4 r = rm1[q8];
                v64[32 + 4 * q8 + 0] = cf * fmaxf(fmaf(s_ab[4 * q8 + 0], r.x, s_ab[32 + 4 * q8 + 0]), 0.f);
                v64[32 + 4 * q8 + 1] = cf * fmaxf(fmaf(s_ab[4 * q8 + 1], r.y, s_ab[32 + 4 * q8 + 1]), 0.f);
                v64[32 + 4 * q8 + 2] = cf * fmaxf(fmaf(s_ab[4 * q8 + 2], r.z, s_ab[32 + 4 * q8 + 2]), 0.f);
                v64[32 + 4 * q8 + 3] = cf * fmaxf(fmaf(s_ab[4 * q8 + 3], r.w, s_ab[32 + 4 * q8 + 3]), 0.f);
            }
            __syncthreads();
            block_reduce_add<64>(v64, s_red, g_st2 + 64, tid);
        }
    }
}

// ---------------- fin2: BN affine params, layer 2 (mu via sum_x @ W2) -------
__global__ void k_fin2(const float* __restrict__ g, const float* __restrict__ b,
                       const float* __restrict__ w2, float invn)
{
    int c = threadIdx.x;  // 64
    float mu = 0.f;
    for (int k = 0; k < 64; k++) mu += g_st2[64 + k] * w2[k * 64 + c];
    mu *= invn;
    float m2 = g_st2[c] * invn;
    double var = (double)m2 - (double)mu * (double)mu;
    if (var < 0.0) var = 0.0;
    float a = (float)((double)g[c] / sqrt(var + (double)BN_EPS));
    g_ab2[c] = a;
    g_ab2[64 + c] = fmaf(-mu, a, b[c]);
}

// ---------------- finalize output --------------------------------------------
__global__ void __launch_bounds__(256) k_out(float* __restrict__ out) {
    int i = (blockIdx.x * 256 + threadIdx.x) * 4;
    float4 r = *(const float4*)(g_rawmax2 + i);
    int ch = i & 63;
    float4 o;
    // raw == -FLT_MAX (empty) -> fmaf gives huge negative -> clamped to 0
    o.x = fmaxf(fmaf(g_ab2[ch + 0], r.x, g_ab2[64 + ch + 0]), 0.f);
    o.y = fmaxf(fmaf(g_ab2[ch + 1], r.y, g_ab2[64 + ch + 1]), 0.f);
    o.z = fmaxf(fmaf(g_ab2[ch + 2], r.z, g_ab2[64 + ch + 2]), 0.f);
    o.w = fmaxf(fmaf(g_ab2[ch + 3], r.w, g_ab2[64 + ch + 3]), 0.f);
    *(float4*)(out + i) = o;
}

// ---------------- launch -----------------------------------------------------
extern "C" void kernel_launch(void* const* d_in, const int* in_sizes, int n_in,
                              void* d_out, int out_size)
{
    const float* xyz = (const float*)d_in[0];
    const float* pf  = (const float*)d_in[1];
    const float* w1  = (const float*)d_in[2];
    const float* g1  = (const float*)d_in[3];
    const float* b1  = (const float*)d_in[4];
    const float* w2  = (const float*)d_in[5];
    const float* g2  = (const float*)d_in[6];
    const float* b2  = (const float*)d_in[7];
    const int*  uinv = (const int*)d_in[8];
    float* out = (float*)d_out;
    int n = in_sizes[1];
    float invn = 1.0f / (float)n;

    void* p;
    cudaGetSymbolAddress(&p, g_cnt); cudaMemsetAsync(p, 0, NVOX * sizeof(int));
    cudaGetSymbolAddress(&p, g_st1); cudaMemsetAsync(p, 0, 48 * sizeof(float));
    cudaGetSymbolAddress(&p, g_st2); cudaMemsetAsync(p, 0, 128 * sizeof(float));

    int nb = (n + 255) / 256;
    k_hist<<<nb, 256>>>(uinv, n);
    k_scanA<<<512, 512>>>();
    k_scanB<<<1, 512>>>();
    k_scanC<<<512, 512>>>();
    k_scatter<<<nb, 256>>>(xyz, pf, uinv, n);
    k_pass1<<<NVOX / 128, 128>>>(w1);
    k_fin1<<<1, 32>>>(g1, b1, w1, invn);
    k_pass2<<<NVOX / 128, 128>>>(w1, w2);
    k_fin2<<<1, 64>>>(g2, b2, w2, invn);
    k_out<<<NVOX * 64 / 1024, 256>>>(out);
}

// round 5
// speedup vs baseline: 5.8454x; 5.8454x over previous
#include <cuda_runtime.h>
#include <float.h>

typedef unsigned int u32;
typedef unsigned long long u64;

#define NVOX 262144
#define MAXN 1572864
#define CH 16
#define PMX (-74.88f)
#define PMY (-74.88f)
#define PMZ (-2.0f)
#define VS  (0.32f)
#define BN_EPS 1e-3f

// ---------------- device scratch -------------------------------------------
static __device__ int    g_cnt[NVOX];
static __device__ int    g_start[NVOX];
static __device__ int    g_cursor[NVOX];
static __device__ int    g_bsum[512];
static __device__ int    g_bsumx[512];
static __device__ float4 g_pts[MAXN];       // CSR-ordered (x,y,z,feat)
static __device__ int    g_vox[MAXN];       // voxel id per CSR point
static __device__ float4 g_vmean[NVOX];
static __device__ u32    g_seg1[NVOX * 32]; // encoded raw max, layer 1
static __device__ u32    g_seg2[NVOX * 64]; // encoded raw max, layer 2
static __device__ float  g_h[NVOX * 64];    // per-voxel xup @ W2[32:64,:]
static __device__ float  g_st1[48];         // [0:32) sumsq(y1), [32:43) sum_f
static __device__ float  g_st2[128];        // [0:64) sumsq(y2), [64:128) sum_x
static __device__ float  g_ab1[64];         // [a32 | c32]
static __device__ float  g_ab2[128];        // [a64 | c64]

// ---------------- packed f32x2 ----------------------------------------------
__device__ __forceinline__ u64 pk2(float a, float b) {
    u64 r; asm("mov.b64 %0,{%1,%2};" : "=l"(r) : "f"(a), "f"(b)); return r;
}
__device__ __forceinline__ void upk2(u64 v, float& a, float& b) {
    asm("mov.b64 {%0,%1},%2;" : "=f"(a), "=f"(b) : "l"(v));
}
__device__ __forceinline__ u64 fma2(u64 a, u64 b, u64 c) {
    u64 d; asm("fma.rn.f32x2 %0,%1,%2,%3;" : "=l"(d) : "l"(a), "l"(b), "l"(c)); return d;
}
__device__ __forceinline__ u64 add2(u64 a, u64 b) {
    u64 d; asm("add.rn.f32x2 %0,%1,%2;" : "=l"(d) : "l"(a), "l"(b)); return d;
}

// ---------------- ordered-uint float encoding (0 == empty) ------------------
__device__ __forceinline__ u32 encf(float f) {
    u32 u = __float_as_uint(f);
    return ((int)u < 0) ? ~u : (u | 0x80000000u);
}
__device__ __forceinline__ float decf(u32 e) {
    return __uint_as_float(((int)e < 0) ? (e & 0x7fffffffu) : ~e);
}

// ---------------- feature build + layer-1 matmul ----------------------------
__device__ __forceinline__ void build_feat(float4 q, float mx, float my, float mz,
                                           float f[11])
{
    float px = q.x, py = q.y, pz = q.z;
    float cx = floorf((px - PMX) / VS);
    float cy = floorf((py - PMY) / VS);
    float cz = floorf((pz - PMZ) / VS);
    f[0] = px; f[1] = py; f[2] = pz; f[3] = q.w;
    f[4] = px - mx; f[5] = py - my; f[6] = pz - mz;
    f[7] = px - (cx * VS + (0.5f * VS + PMX));
    f[8] = py - (cy * VS + (0.5f * VS + PMY));
    f[9] = pz - (cz * VS + (0.5f * VS + PMZ));
    f[10] = sqrtf(px * px + py * py + pz * pz);
}

__device__ __forceinline__ void mm1(const u64* __restrict__ s_w1,
                                    const float f[11], u64 y[16])
{
#pragma unroll
    for (int j = 0; j < 16; j++) y[j] = 0ull;
#pragma unroll
    for (int k = 0; k < 11; k++) {
        u64 xk = pk2(f[k], f[k]);
#pragma unroll
        for (int j = 0; j < 16; j++) y[j] = fma2(xk, s_w1[k * 16 + j], y[j]);
    }
}

// ---------------- flush a 32-channel segment max ----------------------------
__device__ __forceinline__ void flush32(u32* __restrict__ row,
                                        const float mx[32], bool owned)
{
    if (owned) {
        uint4* r4 = (uint4*)row;
#pragma unroll
        for (int q = 0; q < 8; q++)
            r4[q] = make_uint4(encf(mx[4 * q]), encf(mx[4 * q + 1]),
                               encf(mx[4 * q + 2]), encf(mx[4 * q + 3]));
    } else {
#pragma unroll
        for (int j = 0; j < 32; j++) atomicMax(&row[j], encf(mx[j]));
    }
}

// ---------------- warp butterfly + lane0 atomicAdd --------------------------
template <int NVAL>
__device__ __forceinline__ void warp_stats(const float (&vals)[NVAL],
                                           float* __restrict__ gdst)
{
    int lane = threadIdx.x & 31;
#pragma unroll
    for (int j = 0; j < NVAL; j++) {
        float v = vals[j];
#pragma unroll
        for (int o = 16; o > 0; o >>= 1) v += __shfl_xor_sync(0xffffffffu, v, o);
        if (lane == 0) atomicAdd(&gdst[j], v);
    }
}

// ---------------- CSR build --------------------------------------------------
__global__ void __launch_bounds__(256) k_hist(const int* __restrict__ uinv, int n) {
    int stride = gridDim.x * 256;
    for (int i = blockIdx.x * 256 + threadIdx.x; i < n; i += stride)
        atomicAdd(&g_cnt[uinv[i]], 1);
}

__global__ void __launch_bounds__(512) k_scanA() {
    __shared__ int sh[512];
    int t = threadIdx.x, g = blockIdx.x * 512 + t;
    int v = g_cnt[g];
    sh[t] = v;
    __syncthreads();
#pragma unroll
    for (int o = 1; o < 512; o <<= 1) {
        int add = (t >= o) ? sh[t - o] : 0;
        __syncthreads();
        sh[t] += add;
        __syncthreads();
    }
    g_start[g] = sh[t] - v;
    if (t == 511) g_bsum[blockIdx.x] = sh[t];
}

__global__ void __launch_bounds__(512) k_scanB() {
    __shared__ int sh[512];
    int t = threadIdx.x;
    int v = g_bsum[t];
    sh[t] = v;
    __syncthreads();
#pragma unroll
    for (int o = 1; o < 512; o <<= 1) {
        int add = (t >= o) ? sh[t - o] : 0;
        __syncthreads();
        sh[t] += add;
        __syncthreads();
    }
    g_bsumx[t] = sh[t] - v;
}

__global__ void __launch_bounds__(512) k_scanC() {
    int g = blockIdx.x * 512 + threadIdx.x;
    int s = g_start[g] + g_bsumx[blockIdx.x];
    g_start[g] = s;
    g_cursor[g] = s;
}

__global__ void __launch_bounds__(256) k_scatter(
    const float* __restrict__ xyz, const float* __restrict__ pf,
    const int* __restrict__ uinv, int n)
{
    int stride = gridDim.x * 256;
    for (int i = blockIdx.x * 256 + threadIdx.x; i < n; i += stride) {
        int v = uinv[i];
        int pos = atomicAdd(&g_cursor[v], 1);
        g_pts[pos] = make_float4(xyz[3 * i + 0], xyz[3 * i + 1], xyz[3 * i + 2], pf[i]);
        g_vox[pos] = v;
    }
}

// ---------------- voxel means -------------------------------------------------
__global__ void __launch_bounds__(256) k_vmn() {
    int v = blockIdx.x * 256 + threadIdx.x;
    int s = g_start[v], c = g_cnt[v];
    float mx = 0.f, my = 0.f, mz = 0.f;
    for (int p = s; p < s + c; p++) {
        float4 q = g_pts[p];
        mx += q.x; my += q.y; mz += q.z;
    }
    float inv = 1.0f / fmaxf((float)c, 1.0f);
    g_vmean[v] = make_float4(mx * inv, my * inv, mz * inv, 0.f);
}

// ---------------- layer 1: chunked point-parallel ---------------------------
__global__ void __launch_bounds__(256) k_L1(const float* __restrict__ w1, int n) {
    __shared__ u64 s_w1[176];
    int tid = threadIdx.x;
    if (tid < 176) s_w1[tid] = ((const u64*)w1)[tid];
    __syncthreads();

    int t = blockIdx.x * 256 + tid;
    int base = t * CH;
    u64 sq[16];
    float sf[11];
#pragma unroll
    for (int j = 0; j < 16; j++) sq[j] = 0ull;
#pragma unroll
    for (int k = 0; k < 11; k++) sf[k] = 0.f;

    if (base < n) {
        int end = min(base + CH, n);
        int vprev = (base > 0) ? g_vox[base - 1] : -1;
        int vcur = -1;
        bool leftopen = false;
        float maxv[32];
        float mx = 0.f, my = 0.f, mz = 0.f;
        for (int p = base; p < end; p++) {
            int v = g_vox[p];
            if (v != vcur) {
                if (vcur >= 0)
                    flush32(g_seg1 + (size_t)vcur * 32, maxv, !leftopen);
                vcur = v;
                leftopen = (p == base) && (v == vprev);
                float4 m = g_vmean[v];
                mx = m.x; my = m.y; mz = m.z;
#pragma unroll
                for (int j = 0; j < 32; j++) maxv[j] = -FLT_MAX;
            }
            float4 q = g_pts[p];
            float f[11]; build_feat(q, mx, my, mz, f);
#pragma unroll
            for (int k = 0; k < 11; k++) sf[k] += f[k];
            u64 y[16]; mm1(s_w1, f, y);
#pragma unroll
            for (int j = 0; j < 16; j++) {
                sq[j] = fma2(y[j], y[j], sq[j]);
                float a, b; upk2(y[j], a, b);
                maxv[2 * j]     = fmaxf(maxv[2 * j], a);
                maxv[2 * j + 1] = fmaxf(maxv[2 * j + 1], b);
            }
        }
        bool rightopen = (end < n) && (g_vox[end] == vcur);
        flush32(g_seg1 + (size_t)vcur * 32, maxv, !leftopen && !rightopen);
    }

    float vals[43];
#pragma unroll
    for (int j = 0; j < 16; j++) upk2(sq[j], vals[2 * j], vals[2 * j + 1]);
#pragma unroll
    for (int k = 0; k < 11; k++) vals[32 + k] = sf[k];
    warp_stats<43>(vals, g_st1);
}

// ---------------- fin1: BN params layer 1 (mu via sum_f @ W1) ---------------
__global__ void k_fin1(const float* __restrict__ g, const float* __restrict__ b,
                       const float* __restrict__ w1, float invn)
{
    int c = threadIdx.x;  // 32
    float mu = 0.f;
#pragma unroll
    for (int k = 0; k < 11; k++) mu += g_st1[32 + k] * w1[k * 32 + c];
    mu *= invn;
    float m2 = g_st1[c] * invn;
    double var = (double)m2 - (double)mu * (double)mu;
    if (var < 0.0) var = 0.0;
    float a = (float)((double)g[c] / sqrt(var + (double)BN_EPS));
    g_ab1[c] = a;
    g_ab1[32 + c] = fmaf(-mu, a, b[c]);
}

// ---------------- k_xup: decode xup, h = xup@W2hi, sum cnt*xup --------------
__global__ void __launch_bounds__(256) k_xup(const float* __restrict__ w2) {
    __shared__ u64 s_wh[1024];    // W2 rows 32..63 (all 64 cols as 32 pairs)
    __shared__ float s_ab[64];
    __shared__ float s_sum[32];
    int tid = threadIdx.x;
    for (int i = tid; i < 1024; i += 256) s_wh[i] = ((const u64*)w2)[1024 + i];
    if (tid < 64) s_ab[tid] = g_ab1[tid];
    if (tid < 32) s_sum[tid] = 0.f;
    __syncthreads();

    int v = blockIdx.x * 256 + tid;
    const uint4* e4 = (const uint4*)(g_seg1 + (size_t)v * 32);
    float xu[32];
#pragma unroll
    for (int q = 0; q < 8; q++) {
        uint4 e = e4[q];
        int ch = 4 * q;
        xu[ch + 0] = e.x ? fmaxf(fmaf(s_ab[ch + 0], decf(e.x), s_ab[32 + ch + 0]), 0.f) : 0.f;
        xu[ch + 1] = e.y ? fmaxf(fmaf(s_ab[ch + 1], decf(e.y), s_ab[32 + ch + 1]), 0.f) : 0.f;
        xu[ch + 2] = e.z ? fmaxf(fmaf(s_ab[ch + 2], decf(e.z), s_ab[32 + ch + 2]), 0.f) : 0.f;
        xu[ch + 3] = e.w ? fmaxf(fmaf(s_ab[ch + 3], decf(e.w), s_ab[32 + ch + 3]), 0.f) : 0.f;
    }
    u64 h[32];
#pragma unroll
    for (int j = 0; j < 32; j++) h[j] = 0ull;
#pragma unroll
    for (int k = 0; k < 32; k++) {
        u64 xk = pk2(xu[k], xu[k]);
        const u64* wr = &s_wh[k * 32];
#pragma unroll
        for (int j = 0; j < 32; j++) h[j] = fma2(xk, wr[j], h[j]);
    }
    u64* hrow = (u64*)g_h + (size_t)v * 32;
#pragma unroll
    for (int j = 0; j < 32; j++) hrow[j] = h[j];

    // sum over points of upper x: sum_v cnt_v * xu_v
    float cf = (float)g_cnt[v];
    int lane = tid & 31;
#pragma unroll
    for (int j = 0; j < 32; j++) {
        float val = cf * xu[j];
#pragma unroll
        for (int o = 16; o > 0; o >>= 1) val += __shfl_xor_sync(0xffffffffu, val, o);
        if (lane == 0) atomicAdd(&s_sum[j], val);
    }
    __syncthreads();
    if (tid < 32) atomicAdd(&g_st2[96 + tid], s_sum[tid]);
}

// ---------------- layer 2 half H: chunked point-parallel --------------------
template <int H>
__global__ void __launch_bounds__(128) k_L2(const float* __restrict__ w1,
                                            const float* __restrict__ w2, int n)
{
    __shared__ u64 s_w2[1024];   // W2 rows 0..31, half-H cols (16 pairs per row)
    __shared__ u64 s_w1[176];
    __shared__ float s_ab[64];
    int tid = threadIdx.x;
    for (int i = tid; i < 1024; i += 128) {
        int k = i >> 4, j = i & 15;
        s_w2[i] = ((const u64*)w2)[k * 32 + H * 16 + j];
    }
    for (int i = tid; i < 176; i += 128) s_w1[i] = ((const u64*)w1)[i];
    if (tid < 64) s_ab[tid] = g_ab1[tid];
    __syncthreads();

    int t = blockIdx.x * 128 + tid;
    int base = t * CH;
    u64 sq[16], sx[16];
#pragma unroll
    for (int j = 0; j < 16; j++) { sq[j] = 0ull; sx[j] = 0ull; }

    if (base < n) {
        int end = min(base + CH, n);
        int vprev = (base > 0) ? g_vox[base - 1] : -1;
        int vcur = -1;
        bool leftopen = false;
        float mxh[32];
        float mx = 0.f, my = 0.f, mz = 0.f;
        u64 cacc[16];
#pragma unroll
        for (int j = 0; j < 16; j++) cacc[j] = 0ull;

        for (int p = base; p < end; p++) {
            int v = g_vox[p];
            if (v != vcur) {
                if (vcur >= 0)
                    flush32(g_seg2 + (size_t)vcur * 64 + H * 32, mxh, !leftopen);
                vcur = v;
                leftopen = (p == base) && (v == vprev);
                float4 m = g_vmean[v];
                mx = m.x; my = m.y; mz = m.z;
                const u64* hrow = (const u64*)g_h + (size_t)v * 32 + H * 16;
#pragma unroll
                for (int j = 0; j < 16; j++) cacc[j] = hrow[j];
#pragma unroll
                for (int j = 0; j < 32; j++) mxh[j] = -FLT_MAX;
            }
            float4 q = g_pts[p];
            float f[11]; build_feat(q, mx, my, mz, f);
            u64 y[16]; mm1(s_w1, f, y);
            float x1[32];
#pragma unroll
            for (int j = 0; j < 16; j++) {
                float ya, yb; upk2(y[j], ya, yb);
                x1[2 * j]     = fmaxf(fmaf(s_ab[2 * j],     ya, s_ab[32 + 2 * j]),     0.f);
                x1[2 * j + 1] = fmaxf(fmaf(s_ab[2 * j + 1], yb, s_ab[32 + 2 * j + 1]), 0.f);
                if (H == 0) sx[j] = add2(sx[j], pk2(x1[2 * j], x1[2 * j + 1]));
            }
            u64 acc[16];
#pragma unroll
            for (int j = 0; j < 16; j++) acc[j] = cacc[j];
#pragma unroll
            for (int k = 0; k < 32; k++) {
                u64 xk = pk2(x1[k], x1[k]);
                const u64* wr = &s_w2[k * 16];
#pragma unroll
                for (int j = 0; j < 16; j++) acc[j] = fma2(xk, wr[j], acc[j]);
            }
#pragma unroll
            for (int j = 0; j < 16; j++) {
                sq[j] = fma2(acc[j], acc[j], sq[j]);
                float a, b; upk2(acc[j], a, b);
                mxh[2 * j]     = fmaxf(mxh[2 * j], a);
                mxh[2 * j + 1] = fmaxf(mxh[2 * j + 1], b);
            }
        }
        bool rightopen = (end < n) && (g_vox[end] == vcur);
        flush32(g_seg2 + (size_t)vcur * 64 + H * 32, mxh, !leftopen && !rightopen);
    }

    float v32[32];
#pragma unroll
    for (int j = 0; j < 16; j++) upk2(sq[j], v32[2 * j], v32[2 * j + 1]);
    warp_stats<32>(v32, g_st2 + H * 32);
    if (H == 0) {
#pragma unroll
        for (int j = 0; j < 16; j++) upk2(sx[j], v32[2 * j], v32[2 * j + 1]);
        warp_stats<32>(v32, g_st2 + 64);
    }
}

// ---------------- fin2: BN params layer 2 (mu via sum_x @ W2) ---------------
__global__ void k_fin2(const float* __restrict__ g, const float* __restrict__ b,
                       const float* __restrict__ w2, float invn)
{
    int c = threadIdx.x;  // 64
    float mu = 0.f;
    for (int k = 0; k < 64; k++) mu += g_st2[64 + k] * w2[k * 64 + c];
    mu *= invn;
    float m2 = g_st2[c] * invn;
    double var = (double)m2 - (double)mu * (double)mu;
    if (var < 0.0) var = 0.0;
    float a = (float)((double)g[c] / sqrt(var + (double)BN_EPS));
    g_ab2[c] = a;
    g_ab2[64 + c] = fmaf(-mu, a, b[c]);
}

// ---------------- finalize output --------------------------------------------
__global__ void __launch_bounds__(256) k_out(float* __restrict__ out) {
    int i = (blockIdx.x * 256 + threadIdx.x) * 4;
    uint4 e = *(const uint4*)(g_seg2 + i);
    int ch = i & 63;
    float4 o;
    o.x = e.x ? fmaxf(fmaf(g_ab2[ch + 0], decf(e.x), g_ab2[64 + ch + 0]), 0.f) : 0.f;
    o.y = e.y ? fmaxf(fmaf(g_ab2[ch + 1], decf(e.y), g_ab2[64 + ch + 1]), 0.f) : 0.f;
    o.z = e.z ? fmaxf(fmaf(g_ab2[ch + 2], decf(e.z), g_ab2[64 + ch + 2]), 0.f) : 0.f;
    o.w = e.w ? fmaxf(fmaf(g_ab2[ch + 3], decf(e.w), g_ab2[64 + ch + 3]), 0.f) : 0.f;
    *(float4*)(out + i) = o;
}

// ---------------- launch -----------------------------------------------------
extern "C" void kernel_launch(void* const* d_in, const int* in_sizes, int n_in,
                              void* d_out, int out_size)
{
    const float* xyz = (const float*)d_in[0];
    const float* pf  = (const float*)d_in[1];
    const float* w1  = (const float*)d_in[2];
    const float* g1  = (const float*)d_in[3];
    const float* b1  = (const float*)d_in[4];
    const float* w2  = (const float*)d_in[5];
    const float* g2  = (const float*)d_in[6];
    const float* b2  = (const float*)d_in[7];
    const int*  uinv = (const int*)d_in[8];
    float* out = (float*)d_out;
    int n = in_sizes[1];
    float invn = 1.0f / (float)n;

    void* p;
    cudaGetSymbolAddress(&p, g_cnt);  cudaMemsetAsync(p, 0, NVOX * sizeof(int));
    cudaGetSymbolAddress(&p, g_seg1); cudaMemsetAsync(p, 0, NVOX * 32 * sizeof(u32));
    cudaGetSymbolAddress(&p, g_seg2); cudaMemsetAsync(p, 0, NVOX * 64 * sizeof(u32));
    cudaGetSymbolAddress(&p, g_st1);  cudaMemsetAsync(p, 0, 48 * sizeof(float));
    cudaGetSymbolAddress(&p, g_st2);  cudaMemsetAsync(p, 0, 128 * sizeof(float));

    int nb = (n + 255) / 256;
    int nthr = (n + CH - 1) / CH;
    k_hist<<<nb, 256>>>(uinv, n);
    k_scanA<<<512, 512>>>();
    k_scanB<<<1, 512>>>();
    k_scanC<<<512, 512>>>();
    k_scatter<<<nb, 256>>>(xyz, pf, uinv, n);
    k_vmn<<<NVOX / 256, 256>>>();
    k_L1<<<(nthr + 255) / 256, 256>>>(w1, n);
    k_fin1<<<1, 32>>>(g1, b1, w1, invn);
    k_xup<<<NVOX / 256, 256>>>(w2);
    k_L2<0><<<(nthr + 127) / 128, 128>>>(w1, w2, n);
    k_L2<1><<<(nthr + 127) / 128, 128>>>(w1, w2, n);
    k_fin2<<<1, 64>>>(g2, b2, w2, invn);
    k_out<<<NVOX * 64 / 1024, 256>>>(out);
}